// round 15
// baseline (speedup 1.0000x reference)
#include <cuda_runtime.h>
#include <cuda_bf16.h>
#include <math.h>

#define NNODES  50000
#define DH      128
#define TOTROWS (2 * NNODES)
#define MAXE    800000
#define HROWS   100096          // 782 * 128

typedef unsigned long long ull;
typedef unsigned int u32;

// ---- device scratch (BSS zero at load; each replay restores zeros) ----
__device__ u32   g_support[(size_t)TOTROWS * DH / 2];   // bf16x2
__device__ u32   g_h[(size_t)HROWS * 64];               // bf16x2 gelu output
__device__ int   g_deg[NNODES];
__device__ int   g_off[NNODES + 1];
__device__ int   g_cursor[NNODES];
__device__ int   g_adj[MAXE];
__device__ float g_acc2[64];
__device__ unsigned int g_done;
__device__ int   g_pflag;

// ---- packed helpers ----
__device__ __forceinline__ ull pack2(float a, float b) {
    ull r; asm("mov.b64 %0, {%1, %2};" : "=l"(r) : "f"(a), "f"(b)); return r;
}
__device__ __forceinline__ void unpack2(ull v, float& a, float& b) {
    asm("mov.b64 {%0, %1}, %2;" : "=f"(a), "=f"(b) : "l"(v));
}
__device__ __forceinline__ void ffma2(ull& d, ull a, ull b) {
    asm("fma.rn.f32x2 %0, %1, %2, %0;" : "+l"(d) : "l"(a), "l"(b));
}
// bf16x2 word -> fp32 pair (lo,hi) in a register pair; pair-allocated by ptxas
__device__ __forceinline__ ull bfpair(u32 v) {
    ull r;
    asm("{ .reg .b32 lo, hi;\n\t"
        "shl.b32 lo, %1, 16;\n\t"
        "and.b32 hi, %1, 0xffff0000;\n\t"
        "mov.b64 %0, {lo, hi}; }"
        : "=l"(r) : "r"(v));
    return r;
}
__device__ __forceinline__ void addf2(ull& d, ull a) {
    asm("add.rn.f32x2 %0, %0, %1;" : "+l"(d) : "l"(a));
}
__device__ __forceinline__ u32 pack_bf16(float lo, float hi) {
    u32 r; asm("cvt.rn.bf16x2.f32 %0, %1, %2;" : "=r"(r) : "f"(hi), "f"(lo)); return r;
}
__device__ __forceinline__ float bf_lo(u32 v) { return __uint_as_float(v << 16); }
__device__ __forceinline__ float bf_hi(u32 v) { return __uint_as_float(v & 0xffff0000u); }

__device__ __forceinline__ float gelu_exact(float v) {
    return 0.5f * v * (1.0f + erff(v * 0.70710678118654752f));
}

__device__ __forceinline__ u32 smem_u32(const void* p) {
    u32 a; asm("{ .reg .u64 t; cvta.to.shared.u64 t, %1; cvt.u32.u64 %0, t; }" : "=r"(a) : "l"(p));
    return a;
}
__device__ __forceinline__ void ldmatrix_x4(u32* r, u32 addr) {
    asm volatile("ldmatrix.sync.aligned.m8n8.x4.shared.b16 {%0,%1,%2,%3}, [%4];"
                 : "=r"(r[0]), "=r"(r[1]), "=r"(r[2]), "=r"(r[3]) : "r"(addr));
}
__device__ __forceinline__ void ldmatrix_x2_trans(u32* r, u32 addr) {
    asm volatile("ldmatrix.sync.aligned.m8n8.x2.trans.shared.b16 {%0,%1}, [%2];"
                 : "=r"(r[0]), "=r"(r[1]) : "r"(addr));
}
__device__ __forceinline__ void mma_bf16(float* c, const u32* a, const u32* b) {
    asm volatile("mma.sync.aligned.m16n8k16.row.col.f32.bf16.bf16.f32 "
                 "{%0,%1,%2,%3}, {%4,%5,%6,%7}, {%8,%9}, {%0,%1,%2,%3};"
                 : "+f"(c[0]), "+f"(c[1]), "+f"(c[2]), "+f"(c[3])
                 : "r"(a[0]), "r"(a[1]), "r"(a[2]), "r"(a[3]), "r"(b[0]), "r"(b[1]));
}

// ---------------------------------------------------------------------------
// K0: merged HMMA GEMM (support = x@W, bf16) + dst histogram.
// ---------------------------------------------------------------------------
#define LDA 136
#define GEMM_BLKS (HROWS / 128)   // 782
#define HIST_BLKS 1024
#define GEMM_SMEM (2 * 128 * LDA * 2)   // 69632 B

__global__ void __launch_bounds__(256, 2)
k_gemm_hist(const float* __restrict__ x, const float* __restrict__ W,
            const int* __restrict__ ei, int nedges) {
    if (blockIdx.x >= GEMM_BLKS) {
        int i = (blockIdx.x - GEMM_BLKS) * blockDim.x + threadIdx.x;
        for (; i < nedges; i += HIST_BLKS * blockDim.x)
            atomicAdd(&g_deg[ei[nedges + i]], 1);
        return;
    }

    extern __shared__ char smem[];
    char* smA = smem;
    char* smB = smem + 128 * LDA * 2;

    int tid  = threadIdx.x;
    int row0 = blockIdx.x * 128;

    #pragma unroll 4
    for (int it = 0; it < 16; it++) {
        int idx = it * 256 + tid;
        int r  = idx >> 5;
        int c4 = idx & 31;
        float4 wv = *(const float4*)(W + r * 128 + c4 * 4);
        *(uint2*)(smB + (r * LDA + c4 * 4) * 2) =
            make_uint2(pack_bf16(wv.x, wv.y), pack_bf16(wv.z, wv.w));
        int grow = row0 + r;
        float4 xv = make_float4(0.f, 0.f, 0.f, 0.f);
        if (grow < TOTROWS) xv = *(const float4*)(x + (size_t)grow * 128 + c4 * 4);
        *(uint2*)(smA + (r * LDA + c4 * 4) * 2) =
            make_uint2(pack_bf16(xv.x, xv.y), pack_bf16(xv.z, xv.w));
    }
    __syncthreads();

    int w    = tid >> 5;
    int lane = tid & 31;
    int wm   = (w >> 2) * 64;
    int wn   = (w & 3) * 32;
    int arow = (lane & 7) + ((lane >> 3) & 1) * 8;
    int kofs = (lane >> 4) * 8;
    int brow = lane & 15;

    u32 sbA = smem_u32(smA);
    u32 sbB = smem_u32(smB);
    u32 aaddr[4], baddr[4];
    #pragma unroll
    for (int mt = 0; mt < 4; mt++)
        aaddr[mt] = sbA + ((wm + mt * 16 + arow) * LDA + kofs) * 2;
    #pragma unroll
    for (int nt = 0; nt < 4; nt++)
        baddr[nt] = sbB + (brow * LDA + wn + nt * 8) * 2;

    float acc[4][4][4];
    #pragma unroll
    for (int mt = 0; mt < 4; mt++)
        #pragma unroll
        for (int nt = 0; nt < 4; nt++)
            #pragma unroll
            for (int q = 0; q < 4; q++) acc[mt][nt][q] = 0.f;

    #pragma unroll
    for (int ks = 0; ks < 8; ks++) {
        u32 a[4][4], b[4][2];
        #pragma unroll
        for (int mt = 0; mt < 4; mt++)
            ldmatrix_x4(a[mt], aaddr[mt] + ks * 32);
        #pragma unroll
        for (int nt = 0; nt < 4; nt++)
            ldmatrix_x2_trans(b[nt], baddr[nt] + ks * 16 * LDA * 2);
        #pragma unroll
        for (int mt = 0; mt < 4; mt++)
            #pragma unroll
            for (int nt = 0; nt < 4; nt++)
                mma_bf16(acc[mt][nt], a[mt], b[nt]);
    }

    int rbase = row0 + wm + (lane >> 2);
    int cbase = (wn >> 1) + (lane & 3);
    #pragma unroll
    for (int mt = 0; mt < 4; mt++) {
        #pragma unroll
        for (int nt = 0; nt < 4; nt++) {
            int r = rbase + mt * 16;
            u32 col = cbase + nt * 4;
            if (r < TOTROWS)
                g_support[(size_t)r * 64 + col] = pack_bf16(acc[mt][nt][0], acc[mt][nt][1]);
            if (r + 8 < TOTROWS)
                g_support[(size_t)(r + 8) * 64 + col] = pack_bf16(acc[mt][nt][2], acc[mt][nt][3]);
        }
    }
}

// ---------------------------------------------------------------------------
// K1: merged prefix + fill. Block 0 (first-wave resident) runs the scan,
// sets g_pflag; all blocks then bucket-fill. 1024 threads/block.
// ---------------------------------------------------------------------------
#define PF_BLKS 201

__global__ void __launch_bounds__(1024, 1)
k_prefix_fill(const int* __restrict__ ei, int nedges) {
    int tid = threadIdx.x;

    if (blockIdx.x == 0) {
        __shared__ int sums[1024];
        const int CH = (NNODES + 1023) / 1024;   // 49
        int beg = tid * CH, end = min(beg + CH, NNODES);
        int s = 0;
        for (int i = beg; i < end; i++) s += g_deg[i];
        sums[tid] = s;
        __syncthreads();
        for (int off = 1; off < 1024; off <<= 1) {
            int add = (tid >= off) ? sums[tid - off] : 0;
            __syncthreads();
            sums[tid] += add;
            __syncthreads();
        }
        int run = sums[tid] - s;
        for (int i = beg; i < end; i++) {
            g_off[i] = run; g_cursor[i] = run;
            run += g_deg[i];
        }
        if (tid == 1023) g_off[NNODES] = sums[1023];
        __threadfence();
        __syncthreads();
        if (tid == 0) atomicExch(&g_pflag, 1);
    } else {
        if (tid == 0) {
            while (atomicAdd(&g_pflag, 0) == 0) { }
        }
        __syncthreads();
    }

    // fill (all blocks)
    for (int i = blockIdx.x * 1024 + tid; i < nedges; i += PF_BLKS * 1024) {
        int src = ei[i];
        int dst = ei[nedges + i];
        int p = atomicAdd(&g_cursor[dst], 1);
        g_adj[p] = src;
    }
}

// ---------------------------------------------------------------------------
// K2: gather + bias + GELU -> g_h. One warp per row; bf16 decode via
// register-pair (SHF+LOP) + add.rn.f32x2 (1 add per bf16x2 word).
// Also re-zeroes g_deg for next replay.
// ---------------------------------------------------------------------------
#define GATHER_BLKS 740

__global__ void __launch_bounds__(256, 5)
k_gather(const float* __restrict__ b) {
    {
        int i = blockIdx.x * blockDim.x + threadIdx.x;
        for (; i < NNODES; i += GATHER_BLKS * 256) g_deg[i] = 0;
    }

    __shared__ float bs[128];
    int tid = threadIdx.x;
    if (tid < 128) bs[tid] = b[tid];
    __syncthreads();

    int w    = tid >> 5;
    int lane = tid & 31;
    float4 bb = ((const float4*)bs)[lane];

    const uint2* sup = (const uint2*)g_support;
    const int nwarps = GATHER_BLKS * 8;

    for (int r = blockIdx.x * 8 + w; r < TOTROWS; r += nwarps) {
        int batch = (r >= NNODES) ? 1 : 0;
        int node  = r - batch * NNODES;
        const uint2* srow = sup + (size_t)batch * NNODES * 32 + lane;

        int beg = g_off[node], end = g_off[node + 1];
        ull acc01 = 0ull, acc23 = 0ull;   // fp32 pairs (cols 4c+0/1, 4c+2/3)

        int j = beg;
        for (; j + 8 <= end; j += 8) {
            int s0 = __ldg(&g_adj[j]);
            int s1 = __ldg(&g_adj[j + 1]);
            int s2 = __ldg(&g_adj[j + 2]);
            int s3 = __ldg(&g_adj[j + 3]);
            int s4 = __ldg(&g_adj[j + 4]);
            int s5 = __ldg(&g_adj[j + 5]);
            int s6 = __ldg(&g_adj[j + 6]);
            int s7 = __ldg(&g_adj[j + 7]);
            uint2 p0 = __ldg(srow + (size_t)s0 * 32);
            uint2 p1 = __ldg(srow + (size_t)s1 * 32);
            uint2 p2 = __ldg(srow + (size_t)s2 * 32);
            uint2 p3 = __ldg(srow + (size_t)s3 * 32);
            uint2 p4 = __ldg(srow + (size_t)s4 * 32);
            uint2 p5 = __ldg(srow + (size_t)s5 * 32);
            uint2 p6 = __ldg(srow + (size_t)s6 * 32);
            uint2 p7 = __ldg(srow + (size_t)s7 * 32);
            addf2(acc01, bfpair(p0.x)); addf2(acc23, bfpair(p0.y));
            addf2(acc01, bfpair(p1.x)); addf2(acc23, bfpair(p1.y));
            addf2(acc01, bfpair(p2.x)); addf2(acc23, bfpair(p2.y));
            addf2(acc01, bfpair(p3.x)); addf2(acc23, bfpair(p3.y));
            addf2(acc01, bfpair(p4.x)); addf2(acc23, bfpair(p4.y));
            addf2(acc01, bfpair(p5.x)); addf2(acc23, bfpair(p5.y));
            addf2(acc01, bfpair(p6.x)); addf2(acc23, bfpair(p6.y));
            addf2(acc01, bfpair(p7.x)); addf2(acc23, bfpair(p7.y));
        }
        for (; j < end; j++) {
            int s0 = __ldg(&g_adj[j]);
            uint2 p0 = __ldg(srow + (size_t)s0 * 32);
            addf2(acc01, bfpair(p0.x));
            addf2(acc23, bfpair(p0.y));
        }

        float ax, ay, az, aw;
        unpack2(acc01, ax, ay);
        unpack2(acc23, az, aw);
        float g0 = gelu_exact(ax + bb.x), g1 = gelu_exact(ay + bb.y);
        float g2 = gelu_exact(az + bb.z), g3 = gelu_exact(aw + bb.w);
        ((uint2*)g_h)[(size_t)r * 32 + lane] =
            make_uint2(pack_bf16(g0, g1), pack_bf16(g2, g3));
    }
}

// ---------------------------------------------------------------------------
// K3 (profiled slot): persistent batched MLP. 261 blocks x 3 tiles (even).
// Layer1 HMMA, layer2 FFMA2, layer3 folded by linearity. Ticket winner
// finalizes and restores zero-state (g_acc2, g_done, g_pflag).
// ---------------------------------------------------------------------------
#define LDH 136
#define LDW 72
#define ST  130
#define MLP_TILES (HROWS / 128)   // 782
#define MLP_BLKS  261
#define SMA_BYTES (128 * LDH * 2)
#define SMW_BYTES (128 * LDW * 2)
#define MLP_SMEM  (SMA_BYTES + SMW_BYTES + 8192 + 256 + 128 + 256)

__global__ void __launch_bounds__(256, 2)
k_mlp(const float* __restrict__ W1, const float* __restrict__ b1,
      const float* __restrict__ W2, const float* __restrict__ b2,
      const float* __restrict__ W3, const float* __restrict__ b3,
      float* __restrict__ out) {
    extern __shared__ char smc[];
    char*  smA  = smc;
    char*  smW  = smc + SMA_BYTES;
    float* W2s  = (float*)(smc + SMA_BYTES + SMW_BYTES);
    float* b1s  = W2s + 2048;
    float* b2s  = b1s + 64;
    float* accs = b2s + 32;

    int tid = threadIdx.x;

    for (int i = tid; i < 2048; i += 256) {
        int k = i >> 4, c4 = i & 15;
        float4 wv = *(const float4*)(W1 + k * 64 + c4 * 4);
        *(uint2*)(smW + (k * LDW + c4 * 4) * 2) =
            make_uint2(pack_bf16(wv.x, wv.y), pack_bf16(wv.z, wv.w));
    }
    for (int i = tid; i < 2048; i += 256) W2s[i] = W2[i];
    if (tid < 64) b1s[tid] = b1[tid];
    if (tid < 32) b2s[tid] = b2[tid];
    if (tid < 64) accs[tid] = 0.f;

    int w    = tid >> 5;
    int lane = tid & 31;
    int wm   = (w >> 2) * 64;
    int wn   = (w & 3) * 16;
    int arow = (lane & 7) + ((lane >> 3) & 1) * 8;
    int kofs = (lane >> 4) * 8;
    int brow = lane & 15;
    int colg = tid & 15;
    int rowg = tid >> 4;

    u32 sA = smem_u32(smA);
    u32 sB = smem_u32(smW);
    u32 aaddr[4], baddr[2];
    #pragma unroll
    for (int mt = 0; mt < 4; mt++)
        aaddr[mt] = sA + ((wm + mt * 16 + arow) * LDH + kofs) * 2;
    #pragma unroll
    for (int nt = 0; nt < 2; nt++)
        baddr[nt] = sB + (brow * LDW + wn + nt * 8) * 2;

    const uint2* hrow = (const uint2*)g_h;
    float* h1sT = (float*)smA;

    for (int tile = blockIdx.x; tile < MLP_TILES; tile += MLP_BLKS) {
        int row0 = tile * 128;
        __syncthreads();

        #pragma unroll 4
        for (int it = 0; it < 16; it++) {
            int idx = it * 256 + tid;
            int r = idx >> 5;
            int c = idx & 31;
            uint2 u = __ldg(hrow + (size_t)(row0 + r) * 32 + c);
            *(uint2*)(smA + (r * LDH + 4 * c) * 2) = u;
        }
        __syncthreads();

        float acc[4][2][4];
        #pragma unroll
        for (int nt = 0; nt < 2; nt++) {
            int col = wn + nt * 8 + 2 * (lane & 3);
            float bv0 = b1s[col], bv1 = b1s[col + 1];
            #pragma unroll
            for (int mt = 0; mt < 4; mt++) {
                acc[mt][nt][0] = bv0; acc[mt][nt][1] = bv1;
                acc[mt][nt][2] = bv0; acc[mt][nt][3] = bv1;
            }
        }
        #pragma unroll
        for (int ks = 0; ks < 8; ks++) {
            u32 a[4][4], bfr[2][2];
            #pragma unroll
            for (int mt = 0; mt < 4; mt++)
                ldmatrix_x4(a[mt], aaddr[mt] + ks * 32);
            #pragma unroll
            for (int nt = 0; nt < 2; nt++)
                ldmatrix_x2_trans(bfr[nt], baddr[nt] + ks * 16 * LDW * 2);
            #pragma unroll
            for (int mt = 0; mt < 4; mt++)
                #pragma unroll
                for (int nt = 0; nt < 2; nt++)
                    mma_bf16(acc[mt][nt], a[mt], bfr[nt]);
        }
        __syncthreads();

        int frow = wm + (lane >> 2);
        #pragma unroll
        for (int mt = 0; mt < 4; mt++) {
            #pragma unroll
            for (int nt = 0; nt < 2; nt++) {
                int col = wn + nt * 8 + 2 * (lane & 3);
                int r = frow + mt * 16;
                h1sT[col * ST + r]           = fmaxf(acc[mt][nt][0], 0.f);
                h1sT[(col + 1) * ST + r]     = fmaxf(acc[mt][nt][1], 0.f);
                h1sT[col * ST + r + 8]       = fmaxf(acc[mt][nt][2], 0.f);
                h1sT[(col + 1) * ST + r + 8] = fmaxf(acc[mt][nt][3], 0.f);
            }
        }
        __syncthreads();

        ull acc2[4][2];
        #pragma unroll
        for (int c = 0; c < 2; c++) {
            float bv = b2s[2 * colg + c];
            ull bp = pack2(bv, bv);
            #pragma unroll
            for (int rp = 0; rp < 4; rp++) acc2[rp][c] = bp;
        }
        #pragma unroll 4
        for (int d = 0; d < 64; d++) {
            float2 w2 = *(const float2*)(W2s + d * 32 + 2 * colg);
            ull ww0 = pack2(w2.x, w2.x);
            ull ww1 = pack2(w2.y, w2.y);
            const ull* xp = (const ull*)(h1sT + d * ST + rowg * 8);
            ull x0 = xp[0], x1 = xp[1], x2 = xp[2], x3 = xp[3];
            ffma2(acc2[0][0], x0, ww0); ffma2(acc2[0][1], x0, ww1);
            ffma2(acc2[1][0], x1, ww0); ffma2(acc2[1][1], x1, ww1);
            ffma2(acc2[2][0], x2, ww0); ffma2(acc2[2][1], x2, ww1);
            ffma2(acc2[3][0], x3, ww0); ffma2(acc2[3][1], x3, ww1);
        }

        #pragma unroll
        for (int c = 0; c < 2; c++) {
            float s0 = 0.f, s1 = 0.f;
            #pragma unroll
            for (int rp = 0; rp < 4; rp++) {
                float lo, hi; unpack2(acc2[rp][c], lo, hi);
                lo = fmaxf(lo, 0.f); hi = fmaxf(hi, 0.f);
                int r = row0 + rowg * 8 + 2 * rp;
                if (r < NNODES)            s0 += lo;
                else if (r < TOTROWS)      s1 += lo;
                if (r + 1 < NNODES)        s0 += hi;
                else if (r + 1 < TOTROWS)  s1 += hi;
            }
            atomicAdd(&accs[2 * colg + c],      s0);
            atomicAdd(&accs[32 + 2 * colg + c], s1);
        }
    }

    __syncthreads();
    if (tid < 64) atomicAdd(&g_acc2[tid], accs[tid]);
    __threadfence();
    __syncthreads();

    if (tid == 0) {
        unsigned int prev = atomicAdd(&g_done, 1u);
        if (prev == (unsigned int)(gridDim.x - 1)) {
            #pragma unroll
            for (int o = 0; o < 10; o++) {
                float r0 = b3[o], r1 = b3[o];
                for (int c = 0; c < 32; c++) {
                    float wv = W3[c * 10 + o];
                    r0 = fmaf(__ldcg(&g_acc2[c])      * (1.0f / NNODES), wv, r0);
                    r1 = fmaf(__ldcg(&g_acc2[32 + c]) * (1.0f / NNODES), wv, r1);
                }
                out[o]      = r0;
                out[10 + o] = r1;
            }
            #pragma unroll
            for (int c = 0; c < 64; c++) g_acc2[c] = 0.f;
            g_pflag = 0;
            __threadfence();
            g_done = 0u;
        }
    }
}

// ---------------------------------------------------------------------------
extern "C" void kernel_launch(void* const* d_in, const int* in_sizes, int n_in,
                              void* d_out, int out_size) {
    const float* x  = (const float*)d_in[0];
    const int*   ei = (const int*)  d_in[1];
    const float* W  = (const float*)d_in[2];
    const float* b  = (const float*)d_in[3];
    const float* W1 = (const float*)d_in[4];
    const float* b1 = (const float*)d_in[5];
    const float* W2 = (const float*)d_in[6];
    const float* b2 = (const float*)d_in[7];
    const float* W3 = (const float*)d_in[8];
    const float* b3 = (const float*)d_in[9];
    float* out = (float*)d_out;

    int nedges = in_sizes[1] / 2;

    cudaFuncSetAttribute(k_gemm_hist, cudaFuncAttributeMaxDynamicSharedMemorySize, GEMM_SMEM);
    cudaFuncSetAttribute(k_mlp,       cudaFuncAttributeMaxDynamicSharedMemorySize, MLP_SMEM);

    k_gemm_hist  <<<GEMM_BLKS + HIST_BLKS, 256, GEMM_SMEM>>>(x, W, ei, nedges);
    k_prefix_fill<<<PF_BLKS, 1024>>>(ei, nedges);
    k_gather     <<<GATHER_BLKS, 256>>>(b);
    k_mlp        <<<MLP_BLKS, 256, MLP_SMEM>>>(W1, b1, W2, b2, W3, b3, out);
}